// round 11
// baseline (speedup 1.0000x reference)
#include <cuda_runtime.h>
#include <cuda_fp16.h>
#include <cstdint>

#define BATCH 32
#define T_LEN 2048
#define S_DIM 512
#define E_DIM 32
#define SLICES 4          // CTAs per cluster
#define CHAINS 2          // chains interleaved per cluster
#define COLS 128          // output columns per CTA
#define NTHREADS 512
#define EPI_TID 384       // warps 12-15 are epilogue warps (one per SMSP)
#define TARGET_EXP 6
#define VBYTES (SLICES * 64 * 4)   // 1024B per consumer per chain-step
#define ZFBYTES (SLICES * 4 * 4)   // final z: 16 fp32 partials

__device__ int g_obs[BATCH * T_LEN];

__global__ void obs_extract_kernel(const float* __restrict__ inputs) {
    int idx = blockIdx.x * blockDim.x + threadIdx.x;
    if (idx >= BATCH * T_LEN) return;
    const float* p = inputs + (size_t)idx * E_DIM;
    int e = 0;
#pragma unroll
    for (int i = 0; i < E_DIM; i++) {
        if (p[i] > 0.5f) e = i;
    }
    g_obs[idx] = e;
}

__device__ __forceinline__ uint32_t smem_u32(const void* p) {
    uint32_t a;
    asm("{ .reg .u64 t; cvta.to.shared.u64 t, %1; cvt.u32.u64 %0, t; }"
        : "=r"(a) : "l"(p));
    return a;
}

__device__ __forceinline__ uint32_t mapa_u32(uint32_t saddr, uint32_t rank) {
    uint32_t ra;
    asm("mapa.shared::cluster.u32 %0, %1, %2;" : "=r"(ra) : "r"(saddr), "r"(rank));
    return ra;
}

__device__ __forceinline__ void cluster_sync_() {
    asm volatile("barrier.cluster.arrive.aligned;" ::: "memory");
    asm volatile("barrier.cluster.wait.aligned;" ::: "memory");
}

__device__ __forceinline__ void st_async_u32(uint32_t raddr, uint32_t v, uint32_t rmbar) {
    asm volatile(
        "st.async.shared::cluster.mbarrier::complete_tx::bytes.b32 [%0], %1, [%2];"
        :: "r"(raddr), "r"(v), "r"(rmbar) : "memory");
}

// plain remote cluster-smem store (no mbarrier) — consumed >=1 full step later
__device__ __forceinline__ void st_cluster_f32(uint32_t raddr, float v) {
    asm volatile("st.shared::cluster.f32 [%0], %1;" :: "r"(raddr), "f"(v) : "memory");
}

__device__ __forceinline__ void mbar_init(uint32_t mbar, uint32_t cnt) {
    asm volatile("mbarrier.init.shared.b64 [%0], %1;" :: "r"(mbar), "r"(cnt) : "memory");
}

__device__ __forceinline__ void mbar_expect_tx(uint32_t mbar, uint32_t bytes) {
    asm volatile("mbarrier.arrive.expect_tx.shared.b64 _, [%0], %1;"
                 :: "r"(mbar), "r"(bytes) : "memory");
}

__device__ __forceinline__ void mbar_wait_parity(uint32_t mbar, uint32_t parity) {
    asm volatile(
        "{\n\t"
        ".reg .pred P;\n\t"
        "WAIT_%=: \n\t"
        "mbarrier.try_wait.parity.acquire.cluster.shared::cta.b64 P, [%0], %1, 0x989680;\n\t"
        "@!P bra WAIT_%=;\n\t"
        "}"
        :: "r"(mbar), "r"(parity) : "memory");
}

__device__ __forceinline__ float warp_sum32(float v) {
#pragma unroll
    for (int o = 16; o > 0; o >>= 1)
        v += __shfl_xor_sync(0xffffffffu, v, o);
    return v;
}

__global__ void __cluster_dims__(SLICES, 1, 1) __launch_bounds__(NTHREADS, 1)
hmm_forward_kernel(const float* __restrict__ A,
                   const float* __restrict__ Bem,
                   const float* __restrict__ pi,
                   float* __restrict__ out)
{
    __shared__ __align__(16) uint32_t alpha2[CHAINS][2][S_DIM / 2];
    __shared__ __align__(16) float    zbuf[CHAINS][4][SLICES * 4]; // lagged-Z ring
    __shared__ __align__(16) float    zfin[CHAINS][SLICES * 4];
    __shared__ float    bem_t[E_DIM][COLS];
    __shared__ float    part[CHAINS][4][COLS];
    __shared__ float    embias[E_DIM];
    __shared__ int      obs_s[CHAINS * T_LEN];
    __shared__ __align__(8) unsigned long long mbar_store[6]; // v(ch,buf)x4, zfin(ch)x2

    const int tid = threadIdx.x;
    const int w = tid >> 5;
    const int l = tid & 31;
    const int kc = w >> 2;           // matvec: row chunk 0..3
    const int cg = w & 3;            // matvec: col group 0..3
    uint32_t crank;
    asm("mov.u32 %0, %%cluster_ctarank;" : "=r"(crank));
    const int c = (int)crank;
    const int b0 = (blockIdx.x / SLICES) * CHAINS;

    const int jl_mv = cg * 32 + l;          // matvec column within slice
    const int jg_mv = c * COLS + jl_mv;     // global column

    // ---- A slice into registers (persistent fp16x2) ----
    __half2 a2[64];
#pragma unroll
    for (int p = 0; p < 64; p++) {
        float r0 = A[(size_t)(128 * kc + 2 * p) * S_DIM + jg_mv];
        float r1 = A[(size_t)(128 * kc + 2 * p + 1) * S_DIM + jg_mv];
        a2[p] = __floats2half2_rn(r0, r1);
    }

    for (int i = tid; i < E_DIM * COLS; i += NTHREADS) {
        int e = i / COLS, j = i % COLS;
        bem_t[e][j] = Bem[(size_t)(c * COLS + j) * E_DIM + e];
    }
    for (int i = tid; i < CHAINS * T_LEN; i += NTHREADS)
        obs_s[i] = g_obs[b0 * T_LEN + i];

    // ---- per-symbol mean emission ----
    {
        int e = tid >> 4, seg = tid & 15;
        float s = 0.0f;
#pragma unroll 4
        for (int i = 0; i < 32; i++)
            s += Bem[(size_t)(seg * 32 + i) * E_DIM + e];
#pragma unroll
        for (int o = 8; o > 0; o >>= 1)
            s += __shfl_xor_sync(0xffffffffu, s, o);
        if (seg == 0) embias[e] = s * (1.0f / 512.0f);
    }

    const uint32_t val_sa  = smem_u32(&alpha2[0][0][0]);
    const uint32_t z_sa    = smem_u32(&zbuf[0][0][0]);
    const uint32_t zf_sa   = smem_u32(&zfin[0][0]);
    const uint32_t mbar_sa = smem_u32(&mbar_store[0]);
    // mbar: v(ch,buf) = (ch*2+buf)*8 ; zfin(ch) = 32 + ch*8

    if (tid == 0) {
#pragma unroll
        for (int i = 0; i < 6; i++) mbar_init(mbar_sa + i * 8, 1);
        mbar_expect_tx(mbar_sa + 32, ZFBYTES);   // zfin expects, posted once
        mbar_expect_tx(mbar_sa + 40, ZFBYTES);
    }
    __syncthreads();
    cluster_sync_();   // peers' mbarriers + smem ready before any remote store

    uint32_t val_r[SLICES], z_r[SLICES], zf_r[SLICES], mb_r[SLICES];
#pragma unroll
    for (int r = 0; r < SLICES; r++) {
        val_r[r] = mapa_u32(val_sa, (uint32_t)r);
        z_r[r]   = mapa_u32(z_sa, (uint32_t)r);
        zf_r[r]  = mapa_u32(zf_sa, (uint32_t)r);
        mb_r[r]  = mapa_u32(mbar_sa, (uint32_t)r);
    }

    // epilogue-warp constants (valid when tid >= EPI_TID)
    const int wq = w - 12;            // 0..3
    const int co = wq * 32 + l;       // epilogue column (1 col/thread)

    // ---- PROLOGUE: w_0 for both chains into buf 0 ; z(0) -> ring slot 0 ----
    if (tid >= EPI_TID) {
        const float sc0 = (float)(1 << TARGET_EXP);
        float pv = pi[c * COLS + co];
#pragma unroll
        for (int ch = 0; ch < CHAINS; ch++) {
            const int e0 = obs_s[ch * T_LEN];
            float m = pv * bem_t[e0][co] * sc0;
            float mh = __shfl_down_sync(0xffffffffu, m, 1);
            const uint32_t vmb = (uint32_t)((ch * 2) * 8);
            if (!(l & 1)) {
                __half2 h = __floats2half2_rn(m, mh);
                uint32_t hv = *reinterpret_cast<uint32_t*>(&h);
                uint32_t voff = (uint32_t)((ch * 512 + c * 64 + wq * 16 + (l >> 1)) * 4);
#pragma unroll
                for (int r = 0; r < SLICES; r++)
                    st_async_u32(val_r[r] + voff, hv, mb_r[r] + vmb);
            }
            float zs = warp_sum32(m);
            if (l == 0) {
                uint32_t zoff = (uint32_t)((ch * 64 + 0 * 16 + c * 4 + wq) * 4);
#pragma unroll
                for (int r = 0; r < SLICES; r++)
                    st_cluster_f32(z_r[r] + zoff, zs);
            }
        }
    }

    int K[CHAINS], d_prev[CHAINS];
#pragma unroll
    for (int ch = 0; ch < CHAINS; ch++) { K[ch] = TARGET_EXP; d_prev[ch] = 0; }

    for (int t = 0; t < T_LEN - 1; t++) {
        const int buf = t & 1;
        const int nbuf = buf ^ 1;
        const uint32_t par = (uint32_t)((t >> 1) & 1);

        // expects posted by a NON-epilogue warp, for BOTH chains, up front
        if (tid == 0) {
            mbar_expect_tx(mbar_sa + (0 * 2 + buf) * 8, VBYTES);
            mbar_expect_tx(mbar_sa + (1 * 2 + buf) * 8, VBYTES);
        }

#pragma unroll
        for (int ch = 0; ch < CHAINS; ch++) {
            const uint32_t vmb  = (uint32_t)((ch * 2 + buf) * 8);
            const uint32_t nvmb = (uint32_t)((ch * 2 + nbuf) * 8);

            mbar_wait_parity(mbar_sa + vmb, par);

            // ---- matvec (all 16 warps) ----
            __half2 acc0 = __float2half2_rn(0.0f);
            __half2 acc1 = acc0;
            const uint32_t* ab = &alpha2[ch][buf][64 * kc];
#pragma unroll
            for (int m2 = 0; m2 < 32; m2++) {
                uint2 av = *reinterpret_cast<const uint2*>(&ab[2 * m2]);
                acc0 = __hfma2(*reinterpret_cast<__half2*>(&av.x), a2[2 * m2], acc0);
                acc1 = __hfma2(*reinterpret_cast<__half2*>(&av.y), a2[2 * m2 + 1], acc1);
            }
            acc0 = __hadd2(acc0, acc1);
            float2 f0 = __half22float2(acc0);
            part[ch][kc][jl_mv] = f0.x + f0.y;
            __syncthreads();

            // ---- epilogue (warps 12-15) — overlaps the OTHER chain's matvec ----
            if (tid >= EPI_TID) {
                const int zslot = (t == 0) ? 0 : ((t - 1) & 3);
                const float4* zb = reinterpret_cast<const float4*>(&zbuf[ch][zslot][0]);
                float4 q0 = zb[0], q1 = zb[1], q2 = zb[2], q3 = zb[3];
                float Zp = (((q0.x + q0.y) + (q0.z + q0.w)) +
                            ((q1.x + q1.y) + (q1.z + q1.w))) +
                           (((q2.x + q2.y) + (q2.z + q2.w)) +
                            ((q3.x + q3.y) + (q3.z + q3.w)));
                const int en = obs_s[ch * T_LEN + t + 1];
                float Zm;
                int dp;
                if (t == 0) {
                    Zm = Zp * embias[en];
                    dp = 0;
                } else {
                    const int et = obs_s[ch * T_LEN + t];
                    Zm = Zp * embias[et] * embias[en];
                    dp = d_prev[ch];
                }
                int ex = ((__float_as_int(Zm) >> 23) & 255) - 127;
                int d = TARGET_EXP - ex - dp;
                d = d < -48 ? -48 : (d > 48 ? 48 : d);
                float scale = __int_as_float((uint32_t)(d + 127) << 23);
                d_prev[ch] = d;
                K[ch] += d;

                float s = (part[ch][0][co] + part[ch][1][co]) +
                          (part[ch][2][co] + part[ch][3][co]);
                float m = s * bem_t[en][co] * scale;
                float mh = __shfl_down_sync(0xffffffffu, m, 1);
                if (!(l & 1)) {
                    __half2 h = __floats2half2_rn(m, mh);
                    uint32_t hv = *reinterpret_cast<uint32_t*>(&h);
                    uint32_t voff = (uint32_t)((ch * 512 + nbuf * 256 +
                                                c * 64 + wq * 16 + (l >> 1)) * 4);
#pragma unroll
                    for (int r = 0; r < SLICES; r++)
                        st_async_u32(val_r[r] + voff, hv, mb_r[r] + nvmb);
                }
                float zs = warp_sum32(m);
                if (l == 0) {
                    uint32_t zoff = (uint32_t)((ch * 64 + ((t + 1) & 3) * 16 +
                                               c * 4 + wq) * 4);
#pragma unroll
                    for (int r = 0; r < SLICES; r++)
                        st_cluster_f32(z_r[r] + zoff, zs);
                    if (t == T_LEN - 2) {
                        uint32_t zfo = (uint32_t)((ch * 16 + c * 4 + wq) * 4);
#pragma unroll
                        for (int r = 0; r < SLICES; r++)
                            st_async_u32(zf_r[r] + zfo, __float_as_uint(zs),
                                         mb_r[r] + 32 + ch * 8);
                    }
                }
            }
        }
    }

    // ---- FINAL: Z(T-1) via dedicated mbarriers ----
    mbar_wait_parity(mbar_sa + 32, 0);
    mbar_wait_parity(mbar_sa + 40, 0);
    if (c == 0 && tid == EPI_TID) {
#pragma unroll
        for (int ch = 0; ch < CHAINS; ch++) {
            float Z = 0.0f;
#pragma unroll
            for (int i = 0; i < SLICES * 4; i++) Z += zfin[ch][i];
            out[b0 + ch] = (log2f(Z) - (float)K[ch]) * 0.6931471805599453f;
        }
    }
    cluster_sync_();   // no CTA exits while peers may still target its smem
}

extern "C" void kernel_launch(void* const* d_in, const int* in_sizes, int n_in,
                              void* d_out, int out_size)
{
    const float* inputs = (const float*)d_in[0];  // [B,T,E] one-hot
    const float* A      = (const float*)d_in[1];  // [S,S]
    const float* Bem    = (const float*)d_in[2];  // [S,E]
    const float* pi     = (const float*)d_in[3];  // [S]
    float* out = (float*)d_out;                   // [B]

    obs_extract_kernel<<<(BATCH * T_LEN + 255) / 256, 256>>>(inputs);
    hmm_forward_kernel<<<(BATCH / CHAINS) * SLICES, NTHREADS>>>(A, Bem, pi, out);
}

// round 12
// speedup vs baseline: 1.9033x; 1.9033x over previous
#include <cuda_runtime.h>
#include <cuda_fp16.h>
#include <cstdint>

#define BATCH 32
#define T_LEN 2048
#define S_DIM 512
#define E_DIM 32
#define SLICES 4          // CTAs per batch (cluster size)
#define COLS 128          // output columns per CTA
#define NTHREADS 512
#define TARGET_EXP 6      // keep sum(w) ~ 2^6
#define VBYTES (SLICES * 64 * 4)   // 4 slices x 64 half2 words = 1024B
#define ZFBYTES (SLICES * 2 * 4)   // final z: 8 fp32 partials

__device__ int g_obs[BATCH * T_LEN];

__global__ void obs_extract_kernel(const float* __restrict__ inputs) {
    int idx = blockIdx.x * blockDim.x + threadIdx.x;
    if (idx >= BATCH * T_LEN) return;
    const float* p = inputs + (size_t)idx * E_DIM;
    int e = 0;
#pragma unroll
    for (int i = 0; i < E_DIM; i++) {
        if (p[i] > 0.5f) e = i;
    }
    g_obs[idx] = e;
}

__device__ __forceinline__ uint32_t smem_u32(const void* p) {
    uint32_t a;
    asm("{ .reg .u64 t; cvta.to.shared.u64 t, %1; cvt.u32.u64 %0, t; }"
        : "=r"(a) : "l"(p));
    return a;
}

__device__ __forceinline__ uint32_t mapa_u32(uint32_t saddr, uint32_t rank) {
    uint32_t ra;
    asm("mapa.shared::cluster.u32 %0, %1, %2;" : "=r"(ra) : "r"(saddr), "r"(rank));
    return ra;
}

__device__ __forceinline__ void cluster_sync_() {
    asm volatile("barrier.cluster.arrive.aligned;" ::: "memory");
    asm volatile("barrier.cluster.wait.aligned;" ::: "memory");
}

// tx-counted async store (4B) into (remote) cluster smem
__device__ __forceinline__ void st_async_u32(uint32_t raddr, uint32_t v, uint32_t rmbar) {
    asm volatile(
        "st.async.shared::cluster.mbarrier::complete_tx::bytes.b32 [%0], %1, [%2];"
        :: "r"(raddr), "r"(v), "r"(rmbar) : "memory");
}

// plain remote cluster-smem store (no mbarrier) — consumed >=1 full step later
__device__ __forceinline__ void st_cluster_f32(uint32_t raddr, float v) {
    asm volatile("st.shared::cluster.f32 [%0], %1;" :: "r"(raddr), "f"(v) : "memory");
}

__device__ __forceinline__ void mbar_init(uint32_t mbar, uint32_t cnt) {
    asm volatile("mbarrier.init.shared.b64 [%0], %1;" :: "r"(mbar), "r"(cnt) : "memory");
}

__device__ __forceinline__ void mbar_expect_tx(uint32_t mbar, uint32_t bytes) {
    asm volatile("mbarrier.arrive.expect_tx.shared.b64 _, [%0], %1;"
                 :: "r"(mbar), "r"(bytes) : "memory");
}

__device__ __forceinline__ void mbar_wait_parity(uint32_t mbar, uint32_t parity) {
    asm volatile(
        "{\n\t"
        ".reg .pred P;\n\t"
        "WAIT_%=: \n\t"
        "mbarrier.try_wait.parity.acquire.cluster.shared::cta.b64 P, [%0], %1, 0x989680;\n\t"
        "@!P bra WAIT_%=;\n\t"
        "}"
        :: "r"(mbar), "r"(parity) : "memory");
}

__device__ __forceinline__ float warp_sum32(float v) {
#pragma unroll
    for (int o = 16; o > 0; o >>= 1)
        v += __shfl_xor_sync(0xffffffffu, v, o);
    return v;
}

__global__ void __cluster_dims__(SLICES, 1, 1) __launch_bounds__(NTHREADS, 1)
hmm_forward_kernel(const float* __restrict__ A,
                   const float* __restrict__ Bem,
                   const float* __restrict__ pi,
                   float* __restrict__ out)
{
    __shared__ __align__(16) uint32_t alpha2[2][S_DIM / 2]; // packed half2
    __shared__ __align__(16) float    zbuf[4][SLICES * 2];  // lagged-Z ring
    __shared__ __align__(16) float    zfin[SLICES * 2];     // final-step z
    __shared__ float    bem_t[E_DIM][COLS];                 // emission transposed
    __shared__ float    part[4][COLS];                      // per-row-chunk partials
    __shared__ float    embias[E_DIM];                      // mean emission / symbol
    __shared__ int      obs_s[T_LEN];
    __shared__ __align__(8) unsigned long long mbar_store[3]; // v0, v1, zfin

    const int tid = threadIdx.x;
    const int w = tid >> 5;
    const int l = tid & 31;
    const int kc = w >> 2;      // row chunk 0..3 (128 rows each)
    const int cg = w & 3;       // col group 0..3 (32 cols each)
    uint32_t crank;
    asm("mov.u32 %0, %%cluster_ctarank;" : "=r"(crank));
    const int c = (int)crank;
    const int b = blockIdx.x / SLICES;

    const int jl_mv = cg * 32 + l;        // matvec column within slice
    const int jg_mv = c * COLS + jl_mv;   // global column

    // ---- A slice into registers (persistent fp16x2) ----
    __half2 a2[64];
#pragma unroll
    for (int p = 0; p < 64; p++) {
        float r0 = A[(size_t)(128 * kc + 2 * p) * S_DIM + jg_mv];
        float r1 = A[(size_t)(128 * kc + 2 * p + 1) * S_DIM + jg_mv];
        a2[p] = __floats2half2_rn(r0, r1);
    }

    for (int i = tid; i < E_DIM * COLS; i += NTHREADS) {
        int e = i / COLS, j = i % COLS;
        bem_t[e][j] = Bem[(size_t)(c * COLS + j) * E_DIM + e];
    }
    for (int i = tid; i < T_LEN; i += NTHREADS) obs_s[i] = g_obs[b * T_LEN + i];

    // ---- per-symbol mean emission (lagged scale estimate) ----
    {
        int e = tid >> 4, seg = tid & 15;
        float s = 0.0f;
#pragma unroll 4
        for (int i = 0; i < 32; i++)
            s += Bem[(size_t)(seg * 32 + i) * E_DIM + e];
#pragma unroll
        for (int o = 8; o > 0; o >>= 1)
            s += __shfl_xor_sync(0xffffffffu, s, o);
        if (seg == 0) embias[e] = s * (1.0f / 512.0f);
    }

    const uint32_t val_sa  = smem_u32(&alpha2[0][0]);
    const uint32_t z_sa    = smem_u32(&zbuf[0][0]);
    const uint32_t zf_sa   = smem_u32(&zfin[0]);
    const uint32_t mbar_sa = smem_u32(&mbar_store[0]);
    // mbar: v[buf] = buf*8 ; zfin = 16

    if (tid == 0) {
#pragma unroll
        for (int i = 0; i < 3; i++) mbar_init(mbar_sa + i * 8, 1);
        mbar_expect_tx(mbar_sa + 16, ZFBYTES);   // final-z expect, posted once
    }
    __syncthreads();
    cluster_sync_();   // peers' mbarriers + smem ready before any remote store

    uint32_t val_r[SLICES], z_r[SLICES], zf_r[SLICES], mb_r[SLICES];
#pragma unroll
    for (int r = 0; r < SLICES; r++) {
        val_r[r] = mapa_u32(val_sa, (uint32_t)r);
        z_r[r]   = mapa_u32(z_sa, (uint32_t)r);
        zf_r[r]  = mapa_u32(zf_sa, (uint32_t)r);
        mb_r[r]  = mapa_u32(mbar_sa, (uint32_t)r);
    }

    // ---- PROLOGUE: w_0 = 2^TARGET * pi .* em_0 -> buf 0 ; z(0) -> ring slot 0 ----
    if (tid < 64) {
        const int e0 = obs_s[0];
        float2 pp = *reinterpret_cast<const float2*>(&pi[c * COLS + 2 * tid]);
        float2 bm = *reinterpret_cast<const float2*>(&bem_t[e0][2 * tid]);
        const float sc0 = (float)(1 << TARGET_EXP);
        float m0 = pp.x * bm.x * sc0;
        float m1 = pp.y * bm.y * sc0;
        __half2 h = __floats2half2_rn(m0, m1);
        uint32_t hv = *reinterpret_cast<uint32_t*>(&h);
        uint32_t voff = (uint32_t)((c * 64 + tid) * 4);
#pragma unroll
        for (int r = 0; r < SLICES; r++)
            st_async_u32(val_r[r] + voff, hv, mb_r[r] + 0);
        float zs = warp_sum32(m0 + m1);
        if (l == 0) {
            uint32_t zoff = (uint32_t)((c * 2 + w) * 4);  // ring slot 0
#pragma unroll
            for (int r = 0; r < SLICES; r++)
                st_cluster_f32(z_r[r] + zoff, zs);
        }
    }

    int K = TARGET_EXP;
    int d_prev = 0;

    for (int t = 0; t < T_LEN - 1; t++) {
        const int buf = t & 1;
        const int nbuf = buf ^ 1;
        const uint32_t par = (uint32_t)((t >> 1) & 1);

        if (tid == 0) mbar_expect_tx(mbar_sa + buf * 8, VBYTES);

        // ---- scale compute PRE-matvec in warps 0-1 (lagged Z: no wait) ----
        float scale = 0.0f;
        int en = 0;
        if (tid < 64) {
            en = obs_s[t + 1];
            float Zm;
            int dp;
            if (t == 0) {
                // analytic estimate of Z(0): 2^TARGET * mean emission(e0)
                Zm = (float)(1 << TARGET_EXP) * embias[obs_s[0]] * embias[en];
                dp = 0;
            } else {
                const int zslot = (t - 1) & 3;
                const float* zb = &zbuf[zslot][0];
                float2 z0 = *reinterpret_cast<const float2*>(&zb[0]);
                float2 z1 = *reinterpret_cast<const float2*>(&zb[2]);
                float2 z2 = *reinterpret_cast<const float2*>(&zb[4]);
                float2 z3 = *reinterpret_cast<const float2*>(&zb[6]);
                float Zp = ((z0.x + z0.y) + (z1.x + z1.y)) +
                           ((z2.x + z2.y) + (z3.x + z3.y));
                const int et = obs_s[t];
                Zm = Zp * embias[et] * embias[en];
                dp = d_prev;
            }
            int ex = ((__float_as_int(Zm) >> 23) & 255) - 127;
            int d = TARGET_EXP - ex - dp;
            d = d < -48 ? -48 : (d > 48 ? 48 : d);
            scale = __int_as_float((uint32_t)(d + 127) << 23);
            d_prev = d;
            K += d;
        }

        // ---- all warps: wait for values, then matvec ----
        mbar_wait_parity(mbar_sa + buf * 8, par);

        __half2 acc0 = __float2half2_rn(0.0f);
        __half2 acc1 = acc0;
        const uint32_t* ab = &alpha2[buf][64 * kc];
#pragma unroll
        for (int m2 = 0; m2 < 32; m2++) {
            uint2 av = *reinterpret_cast<const uint2*>(&ab[2 * m2]);
            acc0 = __hfma2(*reinterpret_cast<__half2*>(&av.x), a2[2 * m2], acc0);
            acc1 = __hfma2(*reinterpret_cast<__half2*>(&av.y), a2[2 * m2 + 1], acc1);
        }
        acc0 = __hadd2(acc0, acc1);
        float2 f0 = __half22float2(acc0);
        part[kc][jl_mv] = f0.x + f0.y;
        __syncthreads();

        // ---- epilogue (warps 0-1): reduce, scale, ship ----
        if (tid < 64) {
            float2 p0 = *reinterpret_cast<const float2*>(&part[0][2 * tid]);
            float2 p1 = *reinterpret_cast<const float2*>(&part[1][2 * tid]);
            float2 p2 = *reinterpret_cast<const float2*>(&part[2][2 * tid]);
            float2 p3 = *reinterpret_cast<const float2*>(&part[3][2 * tid]);
            float s0 = (p0.x + p1.x) + (p2.x + p3.x);
            float s1 = (p0.y + p1.y) + (p2.y + p3.y);
            float2 bm = *reinterpret_cast<const float2*>(&bem_t[en][2 * tid]);
            float m0 = s0 * bm.x * scale;
            float m1 = s1 * bm.y * scale;
            __half2 h = __floats2half2_rn(m0, m1);
            uint32_t hv = *reinterpret_cast<uint32_t*>(&h);
            uint32_t voff = (uint32_t)((nbuf * 256 + c * 64 + tid) * 4);
#pragma unroll
            for (int r = 0; r < SLICES; r++)
                st_async_u32(val_r[r] + voff, hv, mb_r[r] + nbuf * 8);

            // z-partial ships trail the values — consumed >=1 step later
            float zs = warp_sum32(m0 + m1);
            if (l == 0) {
                uint32_t zoff = (uint32_t)((((t + 1) & 3) * 8 + c * 2 + w) * 4);
#pragma unroll
                for (int r = 0; r < SLICES; r++)
                    st_cluster_f32(z_r[r] + zoff, zs);
                if (t == T_LEN - 2) {
                    uint32_t zfo = (uint32_t)((c * 2 + w) * 4);
#pragma unroll
                    for (int r = 0; r < SLICES; r++)
                        st_async_u32(zf_r[r] + zfo, __float_as_uint(zs),
                                     mb_r[r] + 16);
                }
            }
        }
    }

    // ---- FINAL: Z(T-1) via dedicated mbarrier ----
    mbar_wait_parity(mbar_sa + 16, 0);
    if (c == 0 && tid == 0) {
        float Z = 0.0f;
#pragma unroll
        for (int i = 0; i < SLICES * 2; i++) Z += zfin[i];
        out[b] = (log2f(Z) - (float)K) * 0.6931471805599453f;
    }
    cluster_sync_();   // no CTA exits while peers may still target its smem
}

extern "C" void kernel_launch(void* const* d_in, const int* in_sizes, int n_in,
                              void* d_out, int out_size)
{
    const float* inputs = (const float*)d_in[0];  // [B,T,E] one-hot
    const float* A      = (const float*)d_in[1];  // [S,S]
    const float* Bem    = (const float*)d_in[2];  // [S,E]
    const float* pi     = (const float*)d_in[3];  // [S]
    float* out = (float*)d_out;                   // [B]

    obs_extract_kernel<<<(BATCH * T_LEN + 255) / 256, 256>>>(inputs);
    hmm_forward_kernel<<<BATCH * SLICES, NTHREADS>>>(A, Bem, pi, out);
}